// round 2
// baseline (speedup 1.0000x reference)
#include <cuda_runtime.h>
#include <cstdint>

// VoxelPooling: out[n, :] = mean over k<20 of src_feat[idx(n,k), :]
// idx(n,k) = invoxel_map[n,k], with 0 replaced by invoxel_map[n,0].
//
// Inputs (metadata order):
//   d_in[0] : invoxel_xyz  float32 [N,20,3]   -- UNUSED by the reference
//   d_in[1] : invoxel_map  int32   [N,20]     (JAX demotes int64->int32, x64 off)
//   d_in[2] : src_feat     float32 [M,16]
// Output:
//   d_out   : float32 [N,16]
//
// 4 lanes per voxel, each lane owns one float4 (4 channels). Each (voxel,k)
// gather is 4 lanes x 16B = one contiguous 64B row = exactly 2 sectors.
// All 20 indices preloaded via 5x int4 (row stride 80B, 16B aligned) so the
// 20 gather loads are independent (MLP ~20) and hide L2/DRAM latency.

#define FUSE_K 20

__global__ __launch_bounds__(256) void voxel_pool_kernel(
    const int* __restrict__ invoxel_map,          // [N, FUSE_K] int32
    const float4* __restrict__ src_feat,          // [M, 4] float4 view of [M,16] f32
    float4* __restrict__ out,                     // [N, 4] float4 view of [N,16] f32
    int N)
{
    int t = blockIdx.x * blockDim.x + threadIdx.x;
    int v  = t >> 2;        // voxel index
    int cp = t & 3;         // which float4 chunk of the 16 channels
    if (v >= N) return;

    // ---- load 20 int32 indices as 5 x int4 (row stride 80B is 16B aligned) ----
    const int4* m = reinterpret_cast<const int4*>(invoxel_map + (long long)v * FUSE_K);
    int idx[FUSE_K];
#pragma unroll
    for (int q = 0; q < FUSE_K / 4; q++) {
        int4 p = __ldg(&m[q]);
        idx[q * 4 + 0] = p.x;
        idx[q * 4 + 1] = p.y;
        idx[q * 4 + 2] = p.z;
        idx[q * 4 + 3] = p.w;
    }

    // ---- zero -> group_first substitution ----
    int first = idx[0];
#pragma unroll
    for (int k = 0; k < FUSE_K; k++) {
        idx[k] = (idx[k] == 0) ? first : idx[k];
    }

    // ---- gather + accumulate (independent loads -> deep MLP) ----
    float4 acc = make_float4(0.f, 0.f, 0.f, 0.f);
#pragma unroll
    for (int k = 0; k < FUSE_K; k++) {
        float4 f = __ldg(&src_feat[idx[k] * 4 + cp]);
        acc.x += f.x;
        acc.y += f.y;
        acc.z += f.z;
        acc.w += f.w;
    }

    const float s = 1.0f / (float)FUSE_K;
    acc.x *= s; acc.y *= s; acc.z *= s; acc.w *= s;

    out[(long long)v * 4 + cp] = acc;
}

extern "C" void kernel_launch(void* const* d_in, const int* in_sizes, int n_in,
                              void* d_out, int out_size)
{
    const int*    invoxel_map = (const int*)d_in[1];
    const float4* src_feat    = (const float4*)d_in[2];
    float4*       out         = (float4*)d_out;

    int N = in_sizes[1] / FUSE_K;   // invoxel_map has N*20 elements

    int threads_needed = N * 4;     // 4 lanes per voxel
    int block = 256;
    int grid  = (threads_needed + block - 1) / block;

    voxel_pool_kernel<<<grid, block>>>(invoxel_map, src_feat, out, N);
}

// round 5
// speedup vs baseline: 1.0829x; 1.0829x over previous
#include <cuda_runtime.h>
#include <cstdint>

// VoxelPooling: out[n,:] = mean_{k<20} src_feat[idx(n,k), :]
// idx(n,k) = invoxel_map[n,k] (int32), with 0 replaced by invoxel_map[n,0].
//
// Inputs (metadata order):
//   d_in[0] : invoxel_xyz  float32 [N,20,3]  -- UNUSED
//   d_in[1] : invoxel_map  int32   [N,20]
//   d_in[2] : src_feat     float32 [M,16]    (M = 2e6 -> 128 MB, > L2)
// Output:
//   d_out   : float32 [N,16]
//
// R2 baseline (single pass): gathers thrash L2 -> 1.21 GB DRAM, 190 us.
// This version: two sequential passes over disjoint index halves of
// src_feat. Each pass's gather working set is 64 MB -> L2-resident ->
// gather DRAM collapses to ~one compulsory fill per half. Streaming
// accesses (map, partial out, out) are evict-first so the table keeps L2.

#define FUSE_K 20

__device__ __forceinline__ void load_indices(const int* __restrict__ invoxel_map,
                                             int v, int (&idx)[FUSE_K])
{
    const int4* m = reinterpret_cast<const int4*>(invoxel_map + (long long)v * FUSE_K);
#pragma unroll
    for (int q = 0; q < FUSE_K / 4; q++) {
        int4 p = __ldcs(&m[q]);          // streaming: each map row read once per pass
        idx[q * 4 + 0] = p.x;
        idx[q * 4 + 1] = p.y;
        idx[q * 4 + 2] = p.z;
        idx[q * 4 + 3] = p.w;
    }
    int first = idx[0];
#pragma unroll
    for (int k = 0; k < FUSE_K; k++)
        idx[k] = (idx[k] == 0) ? first : idx[k];
}

__device__ __forceinline__ void gather_half(const float4* __restrict__ src_feat,
                                            const int (&idx)[FUSE_K],
                                            int cp, int lo, int hi, float4& acc)
{
#pragma unroll
    for (int k = 0; k < FUSE_K; k++) {
        int id = idx[k];
        if (id >= lo && id < hi) {        // predicated; in-range loads independent
            float4 f = __ldg(&src_feat[id * 4 + cp]);
            acc.x += f.x;
            acc.y += f.y;
            acc.z += f.z;
            acc.w += f.w;
        }
    }
}

__global__ __launch_bounds__(256) void voxel_pool_pass1(
    const int* __restrict__ invoxel_map,
    const float4* __restrict__ src_feat,
    float4* __restrict__ out,
    int N, int half)
{
    int t = blockIdx.x * blockDim.x + threadIdx.x;
    int v  = t >> 2;
    int cp = t & 3;
    if (v >= N) return;

    int idx[FUSE_K];
    load_indices(invoxel_map, v, idx);

    float4 acc = make_float4(0.f, 0.f, 0.f, 0.f);
    gather_half(src_feat, idx, cp, 0, half, acc);

    __stcs(&out[(long long)v * 4 + cp], acc);          // partial sums (streaming)
}

__global__ __launch_bounds__(256) void voxel_pool_pass2(
    const int* __restrict__ invoxel_map,
    const float4* __restrict__ src_feat,
    float4* __restrict__ out,
    int N, int half, int M)
{
    int t = blockIdx.x * blockDim.x + threadIdx.x;
    int v  = t >> 2;
    int cp = t & 3;
    if (v >= N) return;

    int idx[FUSE_K];
    load_indices(invoxel_map, v, idx);

    float4 acc = __ldcs(&out[(long long)v * 4 + cp]);  // partial sums (streaming)
    gather_half(src_feat, idx, cp, half, M, acc);

    const float s = 1.0f / (float)FUSE_K;
    acc.x *= s; acc.y *= s; acc.z *= s; acc.w *= s;
    __stcs(&out[(long long)v * 4 + cp], acc);
}

extern "C" void kernel_launch(void* const* d_in, const int* in_sizes, int n_in,
                              void* d_out, int out_size)
{
    const int*    invoxel_map = (const int*)d_in[1];
    const float4* src_feat    = (const float4*)d_in[2];
    float4*       out         = (float4*)d_out;

    int N = in_sizes[1] / FUSE_K;     // voxels
    int M = in_sizes[2] / 16;         // src_feat rows
    int half = M / 2;

    int threads_needed = N * 4;
    int block = 256;
    int grid  = (threads_needed + block - 1) / block;

    voxel_pool_pass1<<<grid, block>>>(invoxel_map, src_feat, out, N, half);
    voxel_pool_pass2<<<grid, block>>>(invoxel_map, src_feat, out, N, half, M);
}